// round 17
// baseline (speedup 1.0000x reference)
#include <cuda_runtime.h>
#include <cuda_fp16.h>
#include <cstdint>

#define B_  16
#define C_  512
#define HW_ 4096

// ---------------- scratch (__device__ globals: allocation-free) ----------------
__device__ float g_xsum[B_ * C_];
__device__ float g_qv[B_ * C_];
__device__ float g_sk[B_ * C_];
__device__ float g_beff[B_ * C_];
__device__ __half g_wvhi[C_ * C_];               // wv^T fp16 [c][o]
__device__ __half g_whi[(size_t)B_ * C_ * C_];   // W_eff fp16 [b][m][k]
__device__ __half g_xt[(size_t)B_ * HW_ * C_];   // x^T fp16 [b][n][k]

// ---------------- helpers ----------------
__device__ __forceinline__ uint32_t smem_u32(const void* p) {
    uint32_t a;
    asm("{ .reg .u64 t; cvta.to.shared.u64 t, %1; cvt.u32.u64 %0, t; }" : "=r"(a) : "l"(p));
    return a;
}
__device__ __forceinline__ void cp_async16(uint32_t dst, const void* src) {
    asm volatile("cp.async.cg.shared.global [%0], [%1], 16;" :: "r"(dst), "l"(src) : "memory");
}
__device__ __forceinline__ void cp_commit() {
    asm volatile("cp.async.commit_group;" ::: "memory");
}
template <int N>
__device__ __forceinline__ void cp_wait() {
    asm volatile("cp.async.wait_group %0;" :: "n"(N) : "memory");
}
// 128B-row swizzle
__device__ __forceinline__ uint32_t sw128(uint32_t off) { return off ^ ((off >> 3) & 0x70); }

__device__ __forceinline__ void ldsm_x4(uint32_t* r, uint32_t addr) {
    asm volatile("ldmatrix.sync.aligned.m8n8.x4.shared.b16 {%0,%1,%2,%3}, [%4];"
                 : "=r"(r[0]), "=r"(r[1]), "=r"(r[2]), "=r"(r[3]) : "r"(addr));
}
__device__ __forceinline__ void mma16816(float* c, const uint32_t* a, const uint32_t* b) {
    asm volatile(
        "mma.sync.aligned.m16n8k16.row.col.f32.f16.f16.f32 "
        "{%0,%1,%2,%3}, {%4,%5,%6,%7}, {%8,%9}, {%0,%1,%2,%3};"
        : "+f"(c[0]), "+f"(c[1]), "+f"(c[2]), "+f"(c[3])
        : "r"(a[0]), "r"(a[1]), "r"(a[2]), "r"(a[3]), "r"(b[0]), "r"(b[1]));
}

__device__ __forceinline__ float warpSum(float v) {
#pragma unroll
    for (int o = 16; o > 0; o >>= 1) v += __shfl_xor_sync(0xffffffffu, v, o);
    return v;
}
__device__ __forceinline__ float warpMax(float v) {
#pragma unroll
    for (int o = 16; o > 0; o >>= 1) v = fmaxf(v, __shfl_xor_sync(0xffffffffu, v, o));
    return v;
}

// ---------------- kernel A: xsum[b,c] = sum_n x[b,c,n] ----------------
__global__ void k_xsum(const float* __restrict__ x) {
    int row = blockIdx.x;
    const float4* p = (const float4*)(x + (size_t)row * HW_);
    float s = 0.f;
#pragma unroll 4
    for (int i = threadIdx.x; i < HW_ / 4; i += 256) {
        float4 v = p[i];
        s += (v.x + v.y) + (v.z + v.w);
    }
    __shared__ float red[8];
    s = warpSum(s);
    if ((threadIdx.x & 31) == 0) red[threadIdx.x >> 5] = s;
    __syncthreads();
    if (threadIdx.x == 0) {
        float t = 0.f;
#pragma unroll
        for (int i = 0; i < 8; i++) t += red[i];
        g_xsum[row] = t;
    }
}

// ---------------- kernel B: transpose+convert x -> g_xt fp16 [b][n][k] ----------------
__global__ void k_cvtx(const float* __restrict__ x) {
    __shared__ float tile[64][65];
    int b = blockIdx.z;
    int n0 = blockIdx.x * 64;
    int k0 = blockIdx.y * 64;
    int t = threadIdx.x;
    int tr = t >> 4, tc = t & 15;

    const float* src = x + ((size_t)b * C_ + k0) * HW_ + n0;
#pragma unroll
    for (int i = 0; i < 4; i++) {
        int r = tr + i * 16;  // local k
        float4 v = *(const float4*)(src + (size_t)r * HW_ + tc * 4);
        tile[r][tc * 4 + 0] = v.x;
        tile[r][tc * 4 + 1] = v.y;
        tile[r][tc * 4 + 2] = v.z;
        tile[r][tc * 4 + 3] = v.w;
    }
    __syncthreads();
#pragma unroll
    for (int i = 0; i < 4; i++) {
        int n = tr + i * 16;  // local n
        size_t base = ((size_t)(b * HW_ + n0 + n)) * C_ + k0 + tc * 4;
        __half2 h0 = __floats2half2_rn(tile[tc * 4 + 0][n], tile[tc * 4 + 1][n]);
        __half2 h1 = __floats2half2_rn(tile[tc * 4 + 2][n], tile[tc * 4 + 3][n]);
        uint2 u;
        u.x = *(uint32_t*)&h0;
        u.y = *(uint32_t*)&h1;
        *(uint2*)&g_xt[base] = u;
    }
}

// ---------------- kernel C: wv^T -> fp16 [c][o] ----------------
__global__ void k_wvt(const float* __restrict__ wv) {
    __shared__ float tile[64][65];
    int o0 = blockIdx.y * 64;
    int c0 = blockIdx.x * 64;
    int t = threadIdx.x;
    int tr = t >> 4, tc = t & 15;

    const float* src = wv + (size_t)(o0)*C_ + c0;
#pragma unroll
    for (int i = 0; i < 4; i++) {
        int r = tr + i * 16;
        float4 v = *(const float4*)(src + (size_t)r * C_ + tc * 4);
        tile[r][tc * 4 + 0] = v.x;
        tile[r][tc * 4 + 1] = v.y;
        tile[r][tc * 4 + 2] = v.z;
        tile[r][tc * 4 + 3] = v.w;
    }
    __syncthreads();
#pragma unroll
    for (int i = 0; i < 4; i++) {
        int c = tr + i * 16;
        size_t base = (size_t)(c0 + c) * C_ + o0 + tc * 4;
        __half2 h0 = __floats2half2_rn(tile[tc * 4 + 0][c], tile[tc * 4 + 1][c]);
        __half2 h1 = __floats2half2_rn(tile[tc * 4 + 2][c], tile[tc * 4 + 3][c]);
        uint2 u;
        u.x = *(uint32_t*)&h0;
        u.y = *(uint32_t*)&h1;
        *(uint2*)&g_wvhi[base] = u;
    }
}

// ---------------- kernel D: qv/sk — 1 warp per output ----------------
__global__ void k_qvsk(const float* __restrict__ wq, const float* __restrict__ bq,
                       const float* __restrict__ wk, const float* __restrict__ bk,
                       const float* __restrict__ y) {
    int b = blockIdx.y;
    __shared__ float ys[C_], xs[C_];
    for (int i = threadIdx.x; i < C_; i += 256) {
        ys[i] = y[b * C_ + i];
        xs[i] = g_xsum[b * C_ + i];
    }
    __syncthreads();

    int w = threadIdx.x >> 5, lane = threadIdx.x & 31;
    int o = blockIdx.x * 8 + w;
    const float4* wq4 = (const float4*)(wq + (size_t)o * C_);
    const float4* wk4 = (const float4*)(wk + (size_t)o * C_);
    float aq = 0.f, ak = 0.f;
#pragma unroll
    for (int i = 0; i < 4; i++) {
        int c = lane + 32 * i;
        float4 a = wq4[c], k4 = wk4[c];
        const float* yp = &ys[4 * c];
        const float* xp = &xs[4 * c];
        aq += a.x * yp[0] + a.y * yp[1] + a.z * yp[2] + a.w * yp[3];
        ak += k4.x * xp[0] + k4.y * xp[1] + k4.z * xp[2] + k4.w * xp[3];
    }
    aq = warpSum(aq);
    ak = warpSum(ak);
    if (lane == 0) {
        g_qv[b * C_ + o] = aq + bq[o];
        g_sk[b * C_ + o] = ak + (float)HW_ * bk[o];
    }
}

// ---------------- kernel F: W_eff = softmax(qv⊗sk) @ wv^T, fused (+beff) ----------------
// smem layout:
//   [0, 3*16384)            : B stages (wv^T tiles), 16 KB each
//   [49152, 65536)          : A buffer (128 x 64 fp16 attn stage, sw128 rows)
//   [65536, 67584)          : sk[512] fp32
//   [67584, 69632)          : bv[512] fp32
//   [69632, 70144)          : qv[128]
//   [70144, 70656)          : m[128]
//   [70656, 71168)          : inv[128]
#define WB_STAGE 16384
#define WA_OFF   49152
#define WSK_OFF  65536
#define WBV_OFF  67584
#define WQV_OFF  69632
#define WM_OFF   70144
#define WINV_OFF 70656
#define WG_SMEM  71168

__global__ __launch_bounds__(256, 2) void k_wgemm(const float* __restrict__ bv) {
    extern __shared__ char smem[];
    uint32_t sb = smem_u32(smem);
    float* sks  = (float*)(smem + WSK_OFF);
    float* bvs  = (float*)(smem + WBV_OFF);
    float* qvs  = (float*)(smem + WQV_OFF);
    float* ms   = (float*)(smem + WM_OFF);
    float* invs = (float*)(smem + WINV_OFF);

    int t = threadIdx.x;
    int wid = t >> 5, lane = t & 31;
    int wm = wid & 3, wn = wid >> 2;
    int b = blockIdx.z;
    int tm = blockIdx.y * 128;
    int tn = blockIdx.x * 128;

    const __half* srcBh = g_wvhi + (size_t)tn * C_;

    auto load_stageB = [&](int kt, int st) {
        uint32_t base = sb + st * WB_STAGE;
#pragma unroll
        for (int i = 0; i < 4; i++) {
            int id = t + i * 256;
            int row = id >> 3, c = id & 7;
            uint32_t soff = sw128((uint32_t)(row * 128 + c * 16));
            cp_async16(base + soff, srcBh + (size_t)row * C_ + kt * 64 + c * 8);
        }
        cp_commit();
    };

    // kick off first B stages while we do the softmax prologue
    load_stageB(0, 0);
    load_stageB(1, 1);

    // ---- softmax prologue: per-row m, inv, beff ----
    for (int i = t; i < C_; i += 256) {
        sks[i] = g_sk[b * C_ + i];
        bvs[i] = bv[i];
    }
    if (t < 128) qvs[t] = g_qv[b * C_ + tm + t];
    __syncthreads();

#pragma unroll 1
    for (int j = 0; j < 16; j++) {
        int r = wid * 16 + j;
        float q = qvs[r];
        float mm = -3.4e38f;
#pragma unroll
        for (int i = 0; i < 16; i++) mm = fmaxf(mm, q * sks[lane + 32 * i]);
        mm = warpMax(mm);
        float s = 0.f, sbv = 0.f;
#pragma unroll
        for (int i = 0; i < 16; i++) {
            float ex = __expf(q * sks[lane + 32 * i] - mm);
            s += ex;
            sbv += ex * bvs[lane + 32 * i];
        }
        s = warpSum(s);
        sbv = warpSum(sbv);
        if (lane == 0) {
            ms[r] = mm;
            invs[r] = 1.f / s;
            if (blockIdx.x == 0) g_beff[b * C_ + tm + r] = sbv / s;
        }
    }
    __syncthreads();

    float acc[2][8][4];
#pragma unroll
    for (int mt = 0; mt < 2; mt++)
#pragma unroll
        for (int nt = 0; nt < 8; nt++)
#pragma unroll
            for (int q = 0; q < 4; q++) acc[mt][nt][q] = 0.f;

    int arow = t >> 1;          // A-stage: 2 threads per row
    int akh = t & 1;            // k half (32 of 64)
    float aq = qvs[arow], am = ms[arow], ainv = invs[arow];
    uint32_t Ab = sb + WA_OFF;

#pragma unroll 1
    for (int kt = 0; kt < C_ / 64; kt++) {
        if (kt < C_ / 64 - 2) cp_wait<1>();
        else cp_wait<0>();
        __syncthreads();   // B stage ready; previous iter's A reads done
        if (kt + 2 < C_ / 64) load_stageB(kt + 2, (kt + 2) % 3);

        // ---- compute A stage: attn[tm+row][kt*64 + klocal] -> smem ----
        {
            int kbase = kt * 64 + akh * 32;
#pragma unroll
            for (int cc = 0; cc < 4; cc++) {
                uint32_t h[4];
#pragma unroll
                for (int j = 0; j < 4; j++) {
                    int k = kbase + cc * 8 + 2 * j;
                    float a0 = __expf(aq * sks[k] - am) * ainv;
                    float a1 = __expf(aq * sks[k + 1] - am) * ainv;
                    __half2 hh = __floats2half2_rn(a0, a1);
                    h[j] = *(uint32_t*)&hh;
                }
                int c = akh * 4 + cc;          // chunk index (klocal/8)
                uint32_t off = sw128((uint32_t)(arow * 128 + c * 16));
                asm volatile("st.shared.v4.b32 [%0], {%1,%2,%3,%4};"
                             :: "r"(Ab + off), "r"(h[0]), "r"(h[1]), "r"(h[2]), "r"(h[3])
                             : "memory");
            }
        }
        __syncthreads();   // A stage visible before ldmatrix

        uint32_t Bh = sb + (kt % 3) * WB_STAGE;

#pragma unroll
        for (int s = 0; s < 4; s++) {
            uint32_t ah[2][4];
#pragma unroll
            for (int mt = 0; mt < 2; mt++) {
                int row = wm * 32 + mt * 16 + (lane & 15);
                int ch = 2 * s + (lane >> 4);
                uint32_t off = sw128((uint32_t)(row * 128 + ch * 16));
                ldsm_x4(ah[mt], Ab + off);
            }
            uint32_t bh[8][2];
#pragma unroll
            for (int ng = 0; ng < 4; ng++) {
                int row = wn * 64 + ng * 16 + (lane & 7) + ((lane & 16) >> 1);
                int ch = 2 * s + ((lane >> 3) & 1);
                uint32_t off = sw128((uint32_t)(row * 128 + ch * 16));
                uint32_t r4[4];
                ldsm_x4(r4, Bh + off);
                bh[ng * 2 + 0][0] = r4[0]; bh[ng * 2 + 0][1] = r4[1];
                bh[ng * 2 + 1][0] = r4[2]; bh[ng * 2 + 1][1] = r4[3];
            }
#pragma unroll
            for (int mt = 0; mt < 2; mt++)
#pragma unroll
                for (int nt = 0; nt < 8; nt++)
                    mma16816(acc[mt][nt], ah[mt], bh[nt]);
        }
    }

    int r0 = tm + wm * 32 + (lane >> 2);
    int c0 = tn + wn * 64 + (lane & 3) * 2;
#pragma unroll
    for (int mt = 0; mt < 2; mt++) {
#pragma unroll
        for (int half = 0; half < 2; half++) {
            int row = r0 + mt * 16 + half * 8;
            size_t rbase = ((size_t)(b * C_ + row)) * C_;
#pragma unroll
            for (int nt = 0; nt < 8; nt++) {
                int col = c0 + nt * 8;
                *(__half2*)&g_whi[rbase + col] =
                    __floats2half2_rn(acc[mt][nt][half * 2 + 0], acc[mt][nt][half * 2 + 1]);
            }
        }
    }
}

// ---------------- kernel G: main GEMM + fused epilogue ----------------
#define G_ARR 16384
#define G_STAGE (2 * G_ARR)
#define G_SMEM (3 * G_STAGE)
#define G_NKT (C_ / 64)

__global__ __launch_bounds__(256, 2) void k_main(
    const float* __restrict__ x, float* __restrict__ out,
    const float* __restrict__ gamma) {
    extern __shared__ char smem[];
    uint32_t sb = smem_u32(smem);
    int t = threadIdx.x;
    int wid = t >> 5, lane = t & 31;
    int wm = wid & 3, wn = wid >> 2;
    int b = blockIdx.z;
    int tm = blockIdx.y * 128;
    int tn = blockIdx.x * 128;

    const __half* srcAh = g_whi + ((size_t)b * C_ + tm) * C_;
    const __half* srcBh = g_xt + ((size_t)b * HW_ + tn) * C_;

    auto load_stage = [&](int kt, int st) {
        uint32_t base = sb + st * G_STAGE;
#pragma unroll
        for (int i = 0; i < 4; i++) {
            int id = t + i * 256;
            int row = id >> 3, c = id & 7;
            uint32_t soff = sw128((uint32_t)(row * 128 + c * 16));
            size_t goff = (size_t)row * C_ + kt * 64 + c * 8;
            cp_async16(base + soff, srcAh + goff);
            cp_async16(base + G_ARR + soff, srcBh + goff);
        }
        cp_commit();
    };

    float acc[2][8][4];
#pragma unroll
    for (int mt = 0; mt < 2; mt++)
#pragma unroll
        for (int nt = 0; nt < 8; nt++)
#pragma unroll
            for (int q = 0; q < 4; q++) acc[mt][nt][q] = 0.f;

    load_stage(0, 0);
    load_stage(1, 1);

#pragma unroll 1
    for (int kt = 0; kt < G_NKT; kt++) {
        if (kt < G_NKT - 2) cp_wait<1>();
        else cp_wait<0>();
        __syncthreads();
        if (kt + 2 < G_NKT) load_stage(kt + 2, (kt + 2) % 3);

        uint32_t Ah = sb + (kt % 3) * G_STAGE;
        uint32_t Bh = Ah + G_ARR;

#pragma unroll
        for (int s = 0; s < 4; s++) {
            uint32_t ah[2][4];
#pragma unroll
            for (int mt = 0; mt < 2; mt++) {
                int row = wm * 32 + mt * 16 + (lane & 15);
                int ch = 2 * s + (lane >> 4);
                uint32_t off = sw128((uint32_t)(row * 128 + ch * 16));
                ldsm_x4(ah[mt], Ah + off);
            }
            uint32_t bh[8][2];
#pragma unroll
            for (int ng = 0; ng < 4; ng++) {
                int row = wn * 64 + ng * 16 + (lane & 7) + ((lane & 16) >> 1);
                int ch = 2 * s + ((lane >> 3) & 1);
                uint32_t off = sw128((uint32_t)(row * 128 + ch * 16));
                uint32_t r4[4];
                ldsm_x4(r4, Bh + off);
                bh[ng * 2 + 0][0] = r4[0]; bh[ng * 2 + 0][1] = r4[1];
                bh[ng * 2 + 1][0] = r4[2]; bh[ng * 2 + 1][1] = r4[3];
            }
#pragma unroll
            for (int mt = 0; mt < 2; mt++)
#pragma unroll
                for (int nt = 0; nt < 8; nt++)
                    mma16816(acc[mt][nt], ah[mt], bh[nt]);
        }
    }

    // epilogue: out = gamma*(acc + beff) + x
    float g = *gamma;
    int r0 = tm + wm * 32 + (lane >> 2);
    int c0 = tn + wn * 64 + (lane & 3) * 2;
#pragma unroll
    for (int mt = 0; mt < 2; mt++) {
#pragma unroll
        for (int half = 0; half < 2; half++) {
            int row = r0 + mt * 16 + half * 8;
            float be = g_beff[b * C_ + row];
            const float2* xr = (const float2*)(x + ((size_t)b * C_ + row) * HW_ + c0);
            float2* orow = (float2*)(out + ((size_t)b * C_ + row) * HW_ + c0);
#pragma unroll
            for (int nt = 0; nt < 8; nt++) {
                float2 xv = xr[nt * 4];
                float2 o;
                o.x = g * (acc[mt][nt][half * 2 + 0] + be) + xv.x;
                o.y = g * (acc[mt][nt][half * 2 + 1] + be) + xv.y;
                orow[nt * 4] = o;
            }
        }
    }
}

// ---------------- launch: round-14 DAG, softmax folded into wgemm ----------------
extern "C" void kernel_launch(void* const* d_in, const int* in_sizes, int n_in,
                              void* d_out, int out_size) {
    const float* x = (const float*)d_in[0];
    const float* y = (const float*)d_in[1];
    const float* wq = (const float*)d_in[2];
    const float* bq = (const float*)d_in[3];
    const float* wk = (const float*)d_in[4];
    const float* bk = (const float*)d_in[5];
    const float* wv = (const float*)d_in[6];
    const float* bv = (const float*)d_in[7];
    const float* gamma = (const float*)d_in[8];
    float* out = (float*)d_out;

    static cudaStream_t s2 = nullptr, s3 = nullptr;
    static cudaEvent_t evRoot = nullptr, evCvt = nullptr, evWvt = nullptr;
    static bool configured = false;
    if (!configured) {
        cudaFuncSetAttribute(k_wgemm, cudaFuncAttributeMaxDynamicSharedMemorySize, WG_SMEM);
        cudaFuncSetAttribute(k_main, cudaFuncAttributeMaxDynamicSharedMemorySize, G_SMEM);
        cudaStreamCreateWithFlags(&s2, cudaStreamNonBlocking);
        cudaStreamCreateWithFlags(&s3, cudaStreamNonBlocking);
        cudaEventCreateWithFlags(&evRoot, cudaEventDisableTiming);
        cudaEventCreateWithFlags(&evCvt, cudaEventDisableTiming);
        cudaEventCreateWithFlags(&evWvt, cudaEventDisableTiming);
        configured = true;
    }

    // fork
    cudaEventRecord(evRoot, 0);
    cudaStreamWaitEvent(s2, evRoot, 0);
    cudaStreamWaitEvent(s3, evRoot, 0);

    // branch s2: x transpose/convert (feeds only k_main)
    k_cvtx<<<dim3(HW_ / 64, C_ / 64, B_), 256, 0, s2>>>(x);
    cudaEventRecord(evCvt, s2);

    // branch s3: wv transpose/convert (feeds k_wgemm)
    k_wvt<<<dim3(C_ / 64, C_ / 64), 256, 0, s3>>>(wv);
    cudaEventRecord(evWvt, s3);

    // main chain on stream 0
    k_xsum<<<B_ * C_, 256>>>(x);
    k_qvsk<<<dim3(C_ / 8, B_), 256>>>(wq, bq, wk, bk, y);
    cudaStreamWaitEvent(0, evWvt, 0);
    k_wgemm<<<dim3(C_ / 128, C_ / 128, B_), 256, WG_SMEM>>>(bv);
    cudaStreamWaitEvent(0, evCvt, 0);
    k_main<<<dim3(HW_ / 128, C_ / 128, B_), 256, G_SMEM>>>(x, out, gamma);
}